// round 4
// baseline (speedup 1.0000x reference)
#include <cuda_runtime.h>

#define HID 100
#define T   10
#define NB  5
#define G3  300          // 3*HID
#define BT  64           // batch tile per CTA
#define NTHREADS 512
#define B_MAX 65536

// SMEM float offsets (shared layout across kernels)
#define OFF_WT   0          // 30000 floats: W^T [k=100][g=300]
#define OFF_GH   30000      // 19200 floats: gates [g=300][b=64]
#define OFF_H    49200      // 6400  floats: h     [k=100][b=64]
#define OFF_AUX0 55600      // 300
#define OFF_AUX1 55900      // 300
#define OFF_AUX2 56200      // 300
#define OFF_X    56500      // 64
#define SMEM_FLOATS 56564   // 226256 bytes  (< 227KB limit)

// Scratch (module-static device memory; allocation-free kernel_launch)
__device__ float g_VBUF[(T + NB) * B_MAX];       // sliding value window, [slot][b]
__device__ float g_H1[T * HID * B_MAX];          // layer0 outputs, [t][j][b]
__device__ float g_GI1[T * G3 * B_MAX];          // layer1 input gates, [t][g][b]

__device__ __forceinline__ float sigf(float x)  { return 1.f / (1.f + __expf(-x)); }
__device__ __forceinline__ float tanhf_(float x){ return 1.f - 2.f / (__expf(2.f * x) + 1.f); }

// gates[g][b] = sum_k WtS[k][g] * hS[k][b]   (g in [0,300), b in [0,64))
// 512 threads: warp == one batch-group (rb=4), lanes are gate-lanes (rn=2).
__device__ __forceinline__ void gemm_step(const float* __restrict__ WtS,
                                          const float* __restrict__ hS,
                                          float* __restrict__ ghS, int tid)
{
    const int glane = tid & 31;
    const int bg4   = (tid >> 5) << 2;                 // batch base (multiple of 4)
    const float4* hp = reinterpret_cast<const float4*>(hS) + (bg4 >> 2);

    #pragma unroll
    for (int p = 0; p < 5; ++p) {
        const int g = p * 64 + glane * 2;
        if (g < G3) {
            const float2* wp = reinterpret_cast<const float2*>(WtS) + (g >> 1);
            float a00=0.f, a01=0.f, a10=0.f, a11=0.f;
            float a20=0.f, a21=0.f, a30=0.f, a31=0.f;
            #pragma unroll 10
            for (int k = 0; k < HID; ++k) {
                float4 a = hp[k * 16];          // hS[k*64 + bg4..bg4+3], warp-broadcast
                float2 w = wp[k * 150];         // WtS[k*300 + g, g+1]
                a00 += a.x * w.x;  a01 += a.x * w.y;
                a10 += a.y * w.x;  a11 += a.y * w.y;
                a20 += a.z * w.x;  a21 += a.z * w.y;
                a30 += a.w * w.x;  a31 += a.w * w.y;
            }
            *reinterpret_cast<float4*>(ghS + (g + 0) * 64 + bg4) = make_float4(a00, a10, a20, a30);
            *reinterpret_cast<float4*>(ghS + (g + 1) * 64 + bg4) = make_float4(a01, a11, a21, a31);
        }
    }
}

__device__ __forceinline__ void load_weightT(const float* __restrict__ W, float* __restrict__ WtS, int tid)
{
    for (int idx = tid; idx < G3 * HID; idx += NTHREADS) {
        int row = idx / HID;
        int k   = idx - row * HID;
        WtS[k * G3 + row] = W[idx];              // coalesced global read
    }
}

// ---------------- init: VBUF[s][b] = x[b][s] ----------------
__global__ void k_init(const float* __restrict__ x, int B)
{
    int idx = blockIdx.x * blockDim.x + threadIdx.x;
    if (idx < B * T) {
        int b = idx / T, s = idx - b * T;
        g_VBUF[s * B + b] = x[idx];
    }
}

// ---------------- K1: layer-0 recurrence ----------------
__global__ void __launch_bounds__(NTHREADS, 1)
k_layer0(const float* __restrict__ Whh0, const float* __restrict__ Wih0,
         const float* __restrict__ bih0, const float* __restrict__ bhh0,
         int iter, int B)
{
    extern __shared__ float sm[];
    float* WtS  = sm + OFF_WT;
    float* ghS  = sm + OFF_GH;
    float* hS   = sm + OFF_H;
    float* wihS = sm + OFF_AUX0;
    float* bihS = sm + OFF_AUX1;
    float* bhhS = sm + OFF_AUX2;
    float* xS   = sm + OFF_X;

    const int tid = threadIdx.x;
    const int bg0 = blockIdx.x * BT;

    load_weightT(Whh0, WtS, tid);
    for (int idx = tid; idx < G3; idx += NTHREADS) {
        wihS[idx] = Wih0[idx];
        bihS[idx] = bih0[idx];
        bhhS[idx] = bhh0[idx];
    }
    for (int idx = tid; idx < HID * BT; idx += NTHREADS) hS[idx] = 0.f;
    __syncthreads();

    for (int t = 0; t < T; ++t) {
        if (tid < BT) xS[tid] = g_VBUF[(iter + t) * B + bg0 + tid];
        gemm_step(WtS, hS, ghS, tid);
        __syncthreads();
        for (int idx = tid; idx < HID * BT; idx += NTHREADS) {
            int b = idx & (BT - 1);
            int j = idx >> 6;
            float hr = ghS[(      j) * 64 + b] + bhhS[      j];
            float hz = ghS[(100 + j) * 64 + b] + bhhS[100 + j];
            float hn = ghS[(200 + j) * 64 + b] + bhhS[200 + j];
            float xv = xS[b];
            float r  = sigf (xv * wihS[      j] + bihS[      j] + hr);
            float z  = sigf (xv * wihS[100 + j] + bihS[100 + j] + hz);
            float n  = tanhf_(xv * wihS[200 + j] + bihS[200 + j] + r * hn);
            float hv = hS[idx];
            float hnew = (1.f - z) * n + z * hv;
            hS[idx] = hnew;
            g_H1[(t * HID + j) * B + bg0 + b] = hnew;     // coalesced (batch-minor)
        }
        __syncthreads();
    }
}

// ---------------- K2: GI1[t][g][b] = H1[t][:][b] @ Wih1^T + b_ih1 ----------------
__global__ void __launch_bounds__(NTHREADS, 1)
k_gi1(const float* __restrict__ Wih1, const float* __restrict__ bih1, int B)
{
    extern __shared__ float sm[];
    float* WtS = sm + OFF_WT;
    float* ghS = sm + OFF_GH;
    float* hS  = sm + OFF_H;
    float* bS  = sm + OFF_AUX0;

    const int tid = threadIdx.x;
    const int t   = blockIdx.y;
    const int bg0 = blockIdx.x * BT;

    load_weightT(Wih1, WtS, tid);
    for (int idx = tid; idx < G3; idx += NTHREADS) bS[idx] = bih1[idx];
    for (int idx = tid; idx < HID * BT; idx += NTHREADS) {
        int b = idx & (BT - 1);
        int k = idx >> 6;
        hS[idx] = g_H1[(t * HID + k) * B + bg0 + b];
    }
    __syncthreads();
    gemm_step(WtS, hS, ghS, tid);
    __syncthreads();
    for (int idx = tid; idx < G3 * BT; idx += NTHREADS) {
        int b = idx & (BT - 1);
        int g = idx >> 6;
        g_GI1[(t * G3 + g) * B + bg0 + b] = ghS[idx] + bS[g];
    }
}

// ---------------- K3: layer-1 recurrence + final linear at t=9 ----------------
__global__ void __launch_bounds__(NTHREADS, 1)
k_layer1(const float* __restrict__ Whh1, const float* __restrict__ bhh1,
         const float* __restrict__ Wlin, const float* __restrict__ blin,
         float* __restrict__ out, int iter, int B)
{
    extern __shared__ float sm[];
    float* WtS  = sm + OFF_WT;
    float* ghS  = sm + OFF_GH;
    float* hS   = sm + OFF_H;
    float* bhhS = sm + OFF_AUX0;
    float* wlS  = sm + OFF_AUX1;

    const int tid = threadIdx.x;
    const int bg0 = blockIdx.x * BT;

    load_weightT(Whh1, WtS, tid);
    for (int idx = tid; idx < G3; idx += NTHREADS) bhhS[idx] = bhh1[idx];
    for (int idx = tid; idx < HID; idx += NTHREADS) wlS[idx] = Wlin[idx];
    for (int idx = tid; idx < HID * BT; idx += NTHREADS) hS[idx] = 0.f;
    __syncthreads();

    for (int t = 0; t < T; ++t) {
        gemm_step(WtS, hS, ghS, tid);
        __syncthreads();
        for (int idx = tid; idx < HID * BT; idx += NTHREADS) {
            int b = idx & (BT - 1);
            int j = idx >> 6;
            float ir  = g_GI1[(t * G3 +       j) * B + bg0 + b];   // biases folded in K2
            float iz  = g_GI1[(t * G3 + 100 + j) * B + bg0 + b];
            float inn = g_GI1[(t * G3 + 200 + j) * B + bg0 + b];
            float hr = ghS[(      j) * 64 + b] + bhhS[      j];
            float hz = ghS[(100 + j) * 64 + b] + bhhS[100 + j];
            float hn = ghS[(200 + j) * 64 + b] + bhhS[200 + j];
            float r  = sigf (ir + hr);
            float z  = sigf (iz + hz);
            float n  = tanhf_(inn + r * hn);
            float hv = hS[idx];
            hS[idx] = (1.f - z) * n + z * hv;
        }
        __syncthreads();
    }

    // ret = h2 @ W_lin^T + b_lin  (one thread per batch element)
    if (tid < BT) {
        float acc = blin[0];
        #pragma unroll 10
        for (int k = 0; k < HID; ++k) acc += hS[k * 64 + tid] * wlS[k];
        g_VBUF[(T + iter) * B + bg0 + tid] = acc;      // feeds next iteration's window
        out[(bg0 + tid) * NB + iter] = acc;            // output slot for this iteration
    }
}

extern "C" void kernel_launch(void* const* d_in, const int* in_sizes, int n_in,
                              void* d_out, int out_size)
{
    const float* x    = (const float*)d_in[0];
    const float* Wih0 = (const float*)d_in[1];
    const float* Whh0 = (const float*)d_in[2];
    const float* bih0 = (const float*)d_in[3];
    const float* bhh0 = (const float*)d_in[4];
    const float* Wih1 = (const float*)d_in[5];
    const float* Whh1 = (const float*)d_in[6];
    const float* bih1 = (const float*)d_in[7];
    const float* bhh1 = (const float*)d_in[8];
    const float* Wlin = (const float*)d_in[9];
    const float* blin = (const float*)d_in[10];
    float* out = (float*)d_out;

    const int B = in_sizes[0] / T;          // 65536
    const int smem = SMEM_FLOATS * (int)sizeof(float);

    cudaFuncSetAttribute(k_layer0, cudaFuncAttributeMaxDynamicSharedMemorySize, smem);
    cudaFuncSetAttribute(k_gi1,    cudaFuncAttributeMaxDynamicSharedMemorySize, smem);
    cudaFuncSetAttribute(k_layer1, cudaFuncAttributeMaxDynamicSharedMemorySize, smem);

    k_init<<<(B * T + 511) / 512, 512>>>(x, B);

    const int nblk = B / BT;                // 1024 CTAs
    for (int i = 0; i < NB; ++i) {
        k_layer0<<<nblk, NTHREADS, smem>>>(Whh0, Wih0, bih0, bhh0, i, B);
        k_gi1  <<<dim3(nblk, T), NTHREADS, smem>>>(Wih1, bih1, B);
        k_layer1<<<nblk, NTHREADS, smem>>>(Whh1, bhh1, Wlin, blin, out, i, B);
    }
}